// round 1
// baseline (speedup 1.0000x reference)
#include <cuda_runtime.h>
#include <cstdint>

// ---------------------------------------------------------------------------
// Sparse CNN backbone, fp32, FFMA2 (f32x2) inner loops.
// out[j] = sum_k (in_map[k,j] < n_in) ? feats[in_map[k,j]] @ W[k] : 0
// ---------------------------------------------------------------------------

#define MAXN2 80000
#define MAXN4 13824
#define STATS_BLOCKS 256

__device__ float g_xc[MAXN2 * 32];    // current features (enc1 stage)
__device__ float g_z1[MAXN2 * 32];    // raw conv A output (reused as 64ch in enc2)
__device__ float g_z2[MAXN2 * 32];    // raw conv B output (reused as 64ch in enc2)
__device__ float g_y[MAXN4 * 64];     // current features (enc2 stage)
__device__ float g_part[STATS_BLOCKS * 64 * 2];
__device__ float g_par[128];          // scale[C], shift[C]

__device__ __forceinline__ unsigned long long pack2(float x) {
    unsigned long long r;
    asm("mov.b64 %0, {%1, %1};" : "=l"(r) : "f"(x));
    return r;
}
__device__ __forceinline__ void fma2(unsigned long long& d, unsigned long long a,
                                     unsigned long long b) {
    asm("fma.rn.f32x2 %0, %1, %2, %0;" : "+l"(d) : "l"(a), "l"(b));
}

// ---------------------------------------------------------------------------
// Generic sparse conv: thread = 1 output row x 32 output channels.
// CIN in {32,64}, COUT in {32,64}. TIN: apply relu(x*scale+shift) to gathered
// input rows (folds previous BN+ReLU). ROUT: relu on output.
// ---------------------------------------------------------------------------
template <int CIN, int COUT, bool TIN, bool ROUT>
__global__ __launch_bounds__(128) void conv_k(
    const float* __restrict__ feats, const float* __restrict__ W,
    const int* __restrict__ in_map, const float* __restrict__ bnp, int K,
    int n_in, int n_out, float* __restrict__ out) {
    constexpr int CG = COUT / 32;    // threads per row
    constexpr int ROWS = 128 / CG;   // rows per block
    __shared__ __align__(16) float sW[CIN * COUT];
    __shared__ float sSc[CIN], sSh[CIN];

    const int tid = threadIdx.x;
    const int rl = tid / CG;
    const int cg = tid % CG;
    const int row = blockIdx.x * ROWS + rl;
    const bool rowok = row < n_out;

    if (TIN && tid < CIN) {
        sSc[tid] = bnp[tid];
        sSh[tid] = bnp[CIN + tid];
    }

    unsigned long long acc[16];
#pragma unroll
    for (int i = 0; i < 16; i++) acc[i] = 0ull;

    for (int k = 0; k < K; k++) {
        __syncthreads();
        {
            const float4* Wg = reinterpret_cast<const float4*>(W + (size_t)k * CIN * COUT);
            float4* s4 = reinterpret_cast<float4*>(sW);
#pragma unroll
            for (int i = tid; i < CIN * COUT / 4; i += 128) s4[i] = Wg[i];
        }
        __syncthreads();
        if (rowok) {
            int idx = __ldg(&in_map[(size_t)k * n_out + row]);
            if (idx < n_in) {
                const float4* f4 = reinterpret_cast<const float4*>(feats + (size_t)idx * CIN);
                float fr[CIN];
#pragma unroll
                for (int i = 0; i < CIN / 4; i++) {
                    float4 v = __ldg(&f4[i]);
                    fr[4 * i] = v.x; fr[4 * i + 1] = v.y;
                    fr[4 * i + 2] = v.z; fr[4 * i + 3] = v.w;
                }
                if (TIN) {
#pragma unroll
                    for (int c = 0; c < CIN; c++)
                        fr[c] = fmaxf(fr[c] * sSc[c] + sSh[c], 0.f);
                }
#pragma unroll
                for (int c = 0; c < CIN; c++) {
                    unsigned long long a2 = pack2(fr[c]);
                    const ulonglong2* wrow =
                        reinterpret_cast<const ulonglong2*>(sW + c * COUT + cg * 32);
#pragma unroll
                    for (int p = 0; p < 8; p++) {
                        ulonglong2 w = wrow[p];
                        fma2(acc[2 * p], a2, w.x);
                        fma2(acc[2 * p + 1], a2, w.y);
                    }
                }
            }
        }
    }
    if (rowok) {
        float res[32];
#pragma unroll
        for (int p = 0; p < 16; p++) {
            float2 v = *reinterpret_cast<float2*>(&acc[p]);
            res[2 * p] = ROUT ? fmaxf(v.x, 0.f) : v.x;
            res[2 * p + 1] = ROUT ? fmaxf(v.y, 0.f) : v.y;
        }
        float* op = out + (size_t)row * COUT + cg * 32;
#pragma unroll
        for (int i = 0; i < 8; i++)
            reinterpret_cast<float4*>(op)[i] = reinterpret_cast<float4*>(res)[i];
    }
}

// ---------------------------------------------------------------------------
// First conv: CIN=4 (geo ++ col gathered on the fly), COUT=32, K=125, ReLU out.
// ---------------------------------------------------------------------------
__global__ __launch_bounds__(128) void conv1_k(
    const float* __restrict__ geo, const float* __restrict__ col,
    const float* __restrict__ W,  // [125][4][32]
    const int* __restrict__ in_map, int n_in, int n_out,
    float* __restrict__ out) {
    __shared__ __align__(16) float sW[4 * 32];
    const int tid = threadIdx.x;
    const int row = blockIdx.x * 128 + tid;
    const bool rowok = row < n_out;

    unsigned long long acc[16];
#pragma unroll
    for (int i = 0; i < 16; i++) acc[i] = 0ull;

    for (int k = 0; k < 125; k++) {
        __syncthreads();
        if (tid < 32)
            reinterpret_cast<float4*>(sW)[tid] =
                reinterpret_cast<const float4*>(W + (size_t)k * 128)[tid];
        __syncthreads();
        if (rowok) {
            int idx = __ldg(&in_map[(size_t)k * n_out + row]);
            if (idx < n_in) {
                float fr[4];
                fr[0] = __ldg(&geo[idx]);
                fr[1] = __ldg(&col[(size_t)idx * 3]);
                fr[2] = __ldg(&col[(size_t)idx * 3 + 1]);
                fr[3] = __ldg(&col[(size_t)idx * 3 + 2]);
#pragma unroll
                for (int c = 0; c < 4; c++) {
                    unsigned long long a2 = pack2(fr[c]);
                    const ulonglong2* wrow =
                        reinterpret_cast<const ulonglong2*>(sW + c * 32);
#pragma unroll
                    for (int p = 0; p < 8; p++) {
                        ulonglong2 w = wrow[p];
                        fma2(acc[2 * p], a2, w.x);
                        fma2(acc[2 * p + 1], a2, w.y);
                    }
                }
            }
        }
    }
    if (rowok) {
        float res[32];
#pragma unroll
        for (int p = 0; p < 16; p++) {
            float2 v = *reinterpret_cast<float2*>(&acc[p]);
            res[2 * p] = fmaxf(v.x, 0.f);
            res[2 * p + 1] = fmaxf(v.y, 0.f);
        }
        float* op = out + (size_t)row * 32;
#pragma unroll
        for (int i = 0; i < 8; i++)
            reinterpret_cast<float4*>(op)[i] = reinterpret_cast<float4*>(res)[i];
    }
}

// ---------------------------------------------------------------------------
// BN: deterministic two-stage reduction. Stage 1: per-block per-channel
// partial sum / sumsq. blockDim=256, C divides 256, stride multiple of C
// keeps each thread on a fixed channel.
// ---------------------------------------------------------------------------
__global__ __launch_bounds__(256) void bn_stats(const float* __restrict__ z,
                                                int n, int C,
                                                float* __restrict__ part) {
    __shared__ float sm[512];
    const int tid = threadIdx.x;
    float s = 0.f, ss = 0.f;
    int total = n * C;
    for (int i = blockIdx.x * 256 + tid; i < total; i += gridDim.x * 256) {
        float v = z[i];
        s += v;
        ss += v * v;
    }
    sm[tid] = s;
    sm[256 + tid] = ss;
    __syncthreads();
    for (int off = 128; off >= C; off >>= 1) {
        if (tid < off) {
            sm[tid] += sm[tid + off];
            sm[256 + tid] += sm[256 + tid + off];
        }
        __syncthreads();
    }
    if (tid < C) {
        part[((size_t)blockIdx.x * C + tid) * 2] = sm[tid];
        part[((size_t)blockIdx.x * C + tid) * 2 + 1] = sm[256 + tid];
    }
}

// Stage 2: fold partials -> scale/shift. params[c]=g*rsqrt(var+eps),
// params[C+c]=b-mu*scale.
__global__ void bn_reduce(const float* __restrict__ part, int nblk, int C,
                          int n, const float* __restrict__ g,
                          const float* __restrict__ b,
                          float* __restrict__ params) {
    int c = threadIdx.x;
    if (c < C) {
        float s = 0.f, ss = 0.f;
        for (int i = 0; i < nblk; i++) {
            s += part[((size_t)i * C + c) * 2];
            ss += part[((size_t)i * C + c) * 2 + 1];
        }
        float inv_n = 1.f / (float)n;
        float mu = s * inv_n;
        float var = ss * inv_n - mu * mu;
        float sc = g[c] * rsqrtf(var + 1e-5f);
        params[c] = sc;
        params[C + c] = b[c] - mu * sc;
    }
}

// Finalize a BasicBlock: out = relu(z*scale + shift + res). Vectorized x4.
__global__ __launch_bounds__(256) void bn_res_relu(
    const float4* __restrict__ z, const float* __restrict__ par,
    const float4* __restrict__ res, float4* __restrict__ out, int n, int C) {
    int total = n * C / 4;
    for (int i = blockIdx.x * 256 + threadIdx.x; i < total;
         i += gridDim.x * 256) {
        int cb = (i * 4) % C;
        float4 v = z[i];
        float4 r = res[i];
        v.x = fmaxf(v.x * par[cb] + par[C + cb] + r.x, 0.f);
        v.y = fmaxf(v.y * par[cb + 1] + par[C + cb + 1] + r.y, 0.f);
        v.z = fmaxf(v.z * par[cb + 2] + par[C + cb + 2] + r.z, 0.f);
        v.w = fmaxf(v.w * par[cb + 3] + par[C + cb + 3] + r.w, 0.f);
        out[i] = v;
    }
}

// ---------------------------------------------------------------------------
extern "C" void kernel_launch(void* const* d_in, const int* in_sizes, int n_in,
                              void* d_out, int out_size) {
    const float* x_geo = (const float*)d_in[0];
    const float* x_col = (const float*)d_in[1];
    const float* w0 = (const float*)d_in[2];
    const float* w_e1 = (const float*)d_in[3];
    const float* g_e1 = (const float*)d_in[4];
    const float* b_e1 = (const float*)d_in[5];
    const float* w2 = (const float*)d_in[6];
    const float* w_e2 = (const float*)d_in[7];
    const float* g_e2 = (const float*)d_in[8];
    const float* b_e2 = (const float*)d_in[9];
    const int* m1_in = (const int*)d_in[10];
    const int* m2_in = (const int*)d_in[12];
    const int* m3_in = (const int*)d_in[14];
    const int* m4_in = (const int*)d_in[16];

    const int N = in_sizes[0];          // x_geo elements = N_VOX
    const int n2 = in_sizes[10] / 125;  // stride-2 voxel count
    const int n4 = in_sizes[14] / 27;   // stride-4 voxel count

    float *xc, *z1, *z2, *yb, *part, *par;
    cudaGetSymbolAddress((void**)&xc, g_xc);
    cudaGetSymbolAddress((void**)&z1, g_z1);
    cudaGetSymbolAddress((void**)&z2, g_z2);
    cudaGetSymbolAddress((void**)&yb, g_y);
    cudaGetSymbolAddress((void**)&part, g_part);
    cudaGetSymbolAddress((void**)&par, g_par);

    const int g2 = (n2 + 127) / 128;   // 128 rows/block, COUT=32
    const int g4 = (n4 + 63) / 64;     // 64 rows/block, COUT=64
    const int eg2 = (n2 * 32 / 4 + 255) / 256;
    const int eg4 = (n4 * 64 / 4 + 255) / 256;

    // conv1 (k5 s2, 4->32) + ReLU
    conv1_k<<<g2, 128>>>(x_geo, x_col, w0, m1_in, N, n2, xc);

    // enc1: 2 BasicBlocks, 32ch, maps m2
    for (int i = 0; i < 2; i++) {
        const float* wA = w_e1 + (size_t)(i * 2 + 0) * 27 * 32 * 32;
        const float* wB = w_e1 + (size_t)(i * 2 + 1) * 27 * 32 * 32;
        conv_k<32, 32, false, false><<<g2, 128>>>(xc, wA, m2_in, nullptr, 27, n2, n2, z1);
        bn_stats<<<STATS_BLOCKS, 256>>>(z1, n2, 32, part);
        bn_reduce<<<1, 64>>>(part, STATS_BLOCKS, 32, n2, g_e1 + (size_t)(i * 2) * 32,
                             b_e1 + (size_t)(i * 2) * 32, par);
        // conv B applies BN1+ReLU to its gathered inputs on the fly
        conv_k<32, 32, true, false><<<g2, 128>>>(z1, wB, m2_in, par, 27, n2, n2, z2);
        bn_stats<<<STATS_BLOCKS, 256>>>(z2, n2, 32, part);
        bn_reduce<<<1, 64>>>(part, STATS_BLOCKS, 32, n2,
                             g_e1 + (size_t)(i * 2 + 1) * 32,
                             b_e1 + (size_t)(i * 2 + 1) * 32, par);
        bn_res_relu<<<eg2 < 4096 ? eg2 : 4096, 256>>>(
            (const float4*)z2, par, (const float4*)xc, (float4*)xc, n2, 32);
    }

    // conv2 (32 -> 64, onto stride-4 coords), no activation
    conv_k<32, 64, false, false><<<g4, 128>>>(xc, w2, m3_in, nullptr, 27, n2, n4, yb);

    // enc2: 2 BasicBlocks, 64ch, maps m4
    for (int i = 0; i < 2; i++) {
        const float* wA = w_e2 + (size_t)(i * 2 + 0) * 27 * 64 * 64;
        const float* wB = w_e2 + (size_t)(i * 2 + 1) * 27 * 64 * 64;
        conv_k<64, 64, false, false><<<g4, 128>>>(yb, wA, m4_in, nullptr, 27, n4, n4, z1);
        bn_stats<<<STATS_BLOCKS, 256>>>(z1, n4, 64, part);
        bn_reduce<<<1, 64>>>(part, STATS_BLOCKS, 64, n4, g_e2 + (size_t)(i * 2) * 64,
                             b_e2 + (size_t)(i * 2) * 64, par);
        conv_k<64, 64, true, false><<<g4, 128>>>(z1, wB, m4_in, par, 27, n4, n4, z2);
        bn_stats<<<STATS_BLOCKS, 256>>>(z2, n4, 64, part);
        bn_reduce<<<1, 64>>>(part, STATS_BLOCKS, 64, n4,
                             g_e2 + (size_t)(i * 2 + 1) * 64,
                             b_e2 + (size_t)(i * 2 + 1) * 64, par);
        float* dst = (i == 1) ? (float*)d_out : yb;
        bn_res_relu<<<eg4 < 4096 ? eg4 : 4096, 256>>>(
            (const float4*)z2, par, (const float4*)yb, (float4*)dst, n4, 64);
    }
}

// round 2
// speedup vs baseline: 1.1030x; 1.1030x over previous
#include <cuda_runtime.h>
#include <cstdint>

// ---------------------------------------------------------------------------
// Sparse CNN backbone, fp32, FFMA2 inner loops, all-tap-weights-in-smem convs.
// out[j] = sum_k (in_map[k,j] < n_in) ? feats[in_map[k,j]] @ W[k] : 0
// ---------------------------------------------------------------------------

#define MAXN2 80000
#define MAXN4 13824
#define STATS_BLOCKS 256

__device__ float g_xc[MAXN2 * 32];
__device__ float g_z1[MAXN2 * 32];
__device__ float g_z2[MAXN2 * 32];
__device__ float g_y[MAXN4 * 64];
__device__ float g_part[STATS_BLOCKS * 64 * 2];
__device__ float g_par[128];

typedef unsigned long long ull;

__device__ __forceinline__ ull pack2(float x) {
    ull r;
    asm("mov.b64 %0, {%1, %1};" : "=l"(r) : "f"(x));
    return r;
}
__device__ __forceinline__ void fma2(ull& d, ull a, ull b) {
    asm("fma.rn.f32x2 %0, %1, %2, %0;" : "+l"(d) : "l"(a), "l"(b));
}

// ---------------------------------------------------------------------------
// Generic conv: thread = 1 output row x SLICE output channels.
// All K taps' weight slices staged in smem ONCE; no barriers in k-loop;
// invalid taps skipped. gridDim.y slices COUT. TIN folds prev BN+ReLU into
// the gather.
// ---------------------------------------------------------------------------
template <int CIN, int SLICE, bool TIN>
__global__ __launch_bounds__(256, 2) void conv_t(
    const float* __restrict__ feats, const float* __restrict__ W,
    const int* __restrict__ in_map, const float* __restrict__ bnp, int K,
    int n_in, int n_out, int COUT, float* __restrict__ out) {
    extern __shared__ float sm[];
    float* sW = sm;                      // K*CIN*SLICE floats
    float* sSc = sm + K * CIN * SLICE;   // CIN
    float* sSh = sSc + CIN;

    const int tid = threadIdx.x;
    const int yoff = blockIdx.y * SLICE;
    constexpr int WV = SLICE / 4;

    const int totalv = K * CIN * WV;
    for (int i = tid; i < totalv; i += 256) {
        int r = i / WV, c = i % WV;
        reinterpret_cast<float4*>(sW)[i] =
            *reinterpret_cast<const float4*>(W + (size_t)r * COUT + yoff + 4 * c);
    }
    if (TIN && tid < 2 * CIN) {
        if (tid < CIN) sSc[tid] = bnp[tid];
        else sSh[tid - CIN] = bnp[tid];
    }
    __syncthreads();

    const int row = blockIdx.x * 256 + tid;
    if (row >= n_out) return;

    ull acc[SLICE / 2];
#pragma unroll
    for (int i = 0; i < SLICE / 2; i++) acc[i] = 0ull;

    int idxn = __ldg(&in_map[row]);
    for (int k = 0; k < K; k++) {
        int idx = idxn;
        if (k + 1 < K) idxn = __ldg(&in_map[(size_t)(k + 1) * n_out + row]);
        if (idx >= n_in) continue;

        float fr[CIN];
        const float4* f4 = reinterpret_cast<const float4*>(feats + (size_t)idx * CIN);
#pragma unroll
        for (int i = 0; i < CIN / 4; i++) {
            float4 v = __ldg(&f4[i]);
            fr[4 * i] = v.x; fr[4 * i + 1] = v.y;
            fr[4 * i + 2] = v.z; fr[4 * i + 3] = v.w;
        }
        if (TIN) {
#pragma unroll
            for (int c = 0; c < CIN; c++)
                fr[c] = fmaxf(fr[c] * sSc[c] + sSh[c], 0.f);
        }
        const float* wk = sW + k * CIN * SLICE;
#pragma unroll
        for (int c = 0; c < CIN; c++) {
            ull a2 = pack2(fr[c]);
            const ulonglong2* wrow = reinterpret_cast<const ulonglong2*>(wk + c * SLICE);
#pragma unroll
            for (int p = 0; p < SLICE / 4; p++) {
                ulonglong2 w = wrow[p];
                fma2(acc[2 * p], a2, w.x);
                fma2(acc[2 * p + 1], a2, w.y);
            }
        }
    }

    float res[SLICE];
#pragma unroll
    for (int p = 0; p < SLICE / 2; p++) {
        float2 v = *reinterpret_cast<float2*>(&acc[p]);
        res[2 * p] = v.x;
        res[2 * p + 1] = v.y;
    }
    float* op = out + (size_t)row * COUT + yoff;
#pragma unroll
    for (int i = 0; i < SLICE / 4; i++)
        reinterpret_cast<float4*>(op)[i] = reinterpret_cast<float4*>(res)[i];
}

// ---------------------------------------------------------------------------
// First conv: CIN=4 (geo ++ col gathered on the fly), COUT=32, K=125, ReLU.
// All 125 taps (62.5 KB) staged once; invalid taps (~91%) skipped.
// ---------------------------------------------------------------------------
__global__ __launch_bounds__(256, 3) void conv1_k(
    const float* __restrict__ geo, const float* __restrict__ col,
    const float* __restrict__ W, const int* __restrict__ in_map, int n_in,
    int n_out, float* __restrict__ out) {
    extern __shared__ float sm[];   // 125*4*32 floats
    const int tid = threadIdx.x;
    for (int i = tid; i < 125 * 32; i += 256)
        reinterpret_cast<float4*>(sm)[i] = reinterpret_cast<const float4*>(W)[i];
    __syncthreads();

    const int row = blockIdx.x * 256 + tid;
    if (row >= n_out) return;

    ull acc[16];
#pragma unroll
    for (int i = 0; i < 16; i++) acc[i] = 0ull;

    int idxn = __ldg(&in_map[row]);
    for (int k = 0; k < 125; k++) {
        int idx = idxn;
        if (k + 1 < 125) idxn = __ldg(&in_map[(size_t)(k + 1) * n_out + row]);
        if (idx >= n_in) continue;

        float fr[4];
        fr[0] = __ldg(&geo[idx]);
        fr[1] = __ldg(&col[(size_t)idx * 3]);
        fr[2] = __ldg(&col[(size_t)idx * 3 + 1]);
        fr[3] = __ldg(&col[(size_t)idx * 3 + 2]);
        const float* wk = sm + k * 128;
#pragma unroll
        for (int c = 0; c < 4; c++) {
            ull a2 = pack2(fr[c]);
            const ulonglong2* wrow = reinterpret_cast<const ulonglong2*>(wk + c * 32);
#pragma unroll
            for (int p = 0; p < 8; p++) {
                ulonglong2 w = wrow[p];
                fma2(acc[2 * p], a2, w.x);
                fma2(acc[2 * p + 1], a2, w.y);
            }
        }
    }
    float res[32];
#pragma unroll
    for (int p = 0; p < 16; p++) {
        float2 v = *reinterpret_cast<float2*>(&acc[p]);
        res[2 * p] = fmaxf(v.x, 0.f);
        res[2 * p + 1] = fmaxf(v.y, 0.f);
    }
    float* op = out + (size_t)row * 32;
#pragma unroll
    for (int i = 0; i < 8; i++)
        reinterpret_cast<float4*>(op)[i] = reinterpret_cast<float4*>(res)[i];
}

// ---------------------------------------------------------------------------
// BN stats stage 1: per-block per-channel partial sum / sumsq (deterministic).
// ---------------------------------------------------------------------------
__global__ __launch_bounds__(256) void bn_stats(const float* __restrict__ z,
                                                int n, int C,
                                                float* __restrict__ part) {
    __shared__ float smr[512];
    const int tid = threadIdx.x;
    float s = 0.f, ss = 0.f;
    int total = n * C;
    for (int i = blockIdx.x * 256 + tid; i < total; i += gridDim.x * 256) {
        float v = z[i];
        s += v;
        ss += v * v;
    }
    smr[tid] = s;
    smr[256 + tid] = ss;
    __syncthreads();
    for (int off = 128; off >= C; off >>= 1) {
        if (tid < off) {
            smr[tid] += smr[tid + off];
            smr[256 + tid] += smr[256 + tid + off];
        }
        __syncthreads();
    }
    if (tid < C) {
        part[((size_t)blockIdx.x * C + tid) * 2] = smr[tid];
        part[((size_t)blockIdx.x * C + tid) * 2 + 1] = smr[256 + tid];
    }
}

// Stage 2: parallel fold (deterministic fixed tree) -> scale/shift.
__global__ __launch_bounds__(256) void bn_reduce(
    const float* __restrict__ part, int nblk, int C, int n,
    const float* __restrict__ g, const float* __restrict__ b,
    float* __restrict__ params) {
    __shared__ float ss[256], sq[256];
    const int t = threadIdx.x;
    const int P = 256 / C;
    const int c = t % C, r = t / C;
    float s = 0.f, q = 0.f;
    for (int i = r; i < nblk; i += P) {
        s += part[((size_t)i * C + c) * 2];
        q += part[((size_t)i * C + c) * 2 + 1];
    }
    ss[t] = s;
    sq[t] = q;
    __syncthreads();
    for (int o = P / 2; o >= 1; o >>= 1) {
        if (r < o) {
            ss[t] += ss[t + o * C];
            sq[t] += sq[t + o * C];
        }
        __syncthreads();
    }
    if (r == 0) {
        float inv_n = 1.f / (float)n;
        float mu = ss[t] * inv_n;
        float var = sq[t] * inv_n - mu * mu;
        float sc = g[c] * rsqrtf(var + 1e-5f);
        params[c] = sc;
        params[C + c] = b[c] - mu * sc;
    }
}

// Finalize BasicBlock: out = relu(z*scale + shift + res).
__global__ __launch_bounds__(256) void bn_res_relu(
    const float4* __restrict__ z, const float* __restrict__ par,
    const float4* __restrict__ res, float4* __restrict__ out, int n, int C) {
    int total = n * C / 4;
    for (int i = blockIdx.x * 256 + threadIdx.x; i < total;
         i += gridDim.x * 256) {
        int cb = (i * 4) % C;
        float4 v = z[i];
        float4 r = res[i];
        v.x = fmaxf(v.x * par[cb] + par[C + cb] + r.x, 0.f);
        v.y = fmaxf(v.y * par[cb + 1] + par[C + cb + 1] + r.y, 0.f);
        v.z = fmaxf(v.z * par[cb + 2] + par[C + cb + 2] + r.z, 0.f);
        v.w = fmaxf(v.w * par[cb + 3] + par[C + cb + 3] + r.w, 0.f);
        out[i] = v;
    }
}

// ---------------------------------------------------------------------------
extern "C" void kernel_launch(void* const* d_in, const int* in_sizes, int n_in,
                              void* d_out, int out_size) {
    const float* x_geo = (const float*)d_in[0];
    const float* x_col = (const float*)d_in[1];
    const float* w0 = (const float*)d_in[2];
    const float* w_e1 = (const float*)d_in[3];
    const float* g_e1 = (const float*)d_in[4];
    const float* b_e1 = (const float*)d_in[5];
    const float* w2 = (const float*)d_in[6];
    const float* w_e2 = (const float*)d_in[7];
    const float* g_e2 = (const float*)d_in[8];
    const float* b_e2 = (const float*)d_in[9];
    const int* m1_in = (const int*)d_in[10];
    const int* m2_in = (const int*)d_in[12];
    const int* m3_in = (const int*)d_in[14];
    const int* m4_in = (const int*)d_in[16];

    const int N = in_sizes[0];
    const int n2 = in_sizes[10] / 125;
    const int n4 = in_sizes[14] / 27;

    float *xc, *z1, *z2, *yb, *part, *par;
    cudaGetSymbolAddress((void**)&xc, g_xc);
    cudaGetSymbolAddress((void**)&z1, g_z1);
    cudaGetSymbolAddress((void**)&z2, g_z2);
    cudaGetSymbolAddress((void**)&yb, g_y);
    cudaGetSymbolAddress((void**)&part, g_part);
    cudaGetSymbolAddress((void**)&par, g_par);

    // Opt-in smem sizes (idempotent host calls; capture-safe).
    const int SM1 = 125 * 4 * 32 * 4;                // 64000
    const int SM32 = (27 * 32 * 32 + 64) * 4;        // 110848
    const int SM64 = (27 * 64 * 16 + 128) * 4;       // 111104
    const int SM2 = (27 * 32 * 16 + 64) * 4;         // 55552
    cudaFuncSetAttribute(conv1_k, cudaFuncAttributeMaxDynamicSharedMemorySize, SM1);
    cudaFuncSetAttribute(conv_t<32, 32, false>, cudaFuncAttributeMaxDynamicSharedMemorySize, SM32);
    cudaFuncSetAttribute(conv_t<32, 32, true>, cudaFuncAttributeMaxDynamicSharedMemorySize, SM32);
    cudaFuncSetAttribute(conv_t<64, 16, false>, cudaFuncAttributeMaxDynamicSharedMemorySize, SM64);
    cudaFuncSetAttribute(conv_t<64, 16, true>, cudaFuncAttributeMaxDynamicSharedMemorySize, SM64);
    cudaFuncSetAttribute(conv_t<32, 16, false>, cudaFuncAttributeMaxDynamicSharedMemorySize, SM2);

    const int gx2 = (n2 + 255) / 256;
    const int gx4 = (n4 + 255) / 256;
    const dim3 ge1(gx2, 1), ge2(gx4, 4);
    const int eg2 = (n2 * 32 / 4 + 255) / 256;
    const int eg4 = (n4 * 64 / 4 + 255) / 256;

    // conv1 (k5 s2, 4->32) + ReLU
    conv1_k<<<gx2, 256, SM1>>>(x_geo, x_col, w0, m1_in, N, n2, xc);

    // enc1: 2 BasicBlocks, 32ch
    for (int i = 0; i < 2; i++) {
        const float* wA = w_e1 + (size_t)(i * 2 + 0) * 27 * 32 * 32;
        const float* wB = w_e1 + (size_t)(i * 2 + 1) * 27 * 32 * 32;
        conv_t<32, 32, false><<<ge1, 256, SM32>>>(xc, wA, m2_in, nullptr, 27, n2, n2, 32, z1);
        bn_stats<<<STATS_BLOCKS, 256>>>(z1, n2, 32, part);
        bn_reduce<<<1, 256>>>(part, STATS_BLOCKS, 32, n2,
                              g_e1 + (size_t)(i * 2) * 32, b_e1 + (size_t)(i * 2) * 32, par);
        conv_t<32, 32, true><<<ge1, 256, SM32>>>(z1, wB, m2_in, par, 27, n2, n2, 32, z2);
        bn_stats<<<STATS_BLOCKS, 256>>>(z2, n2, 32, part);
        bn_reduce<<<1, 256>>>(part, STATS_BLOCKS, 32, n2,
                              g_e1 + (size_t)(i * 2 + 1) * 32, b_e1 + (size_t)(i * 2 + 1) * 32, par);
        bn_res_relu<<<eg2 < 4096 ? eg2 : 4096, 256>>>(
            (const float4*)z2, par, (const float4*)xc, (float4*)xc, n2, 32);
    }

    // conv2 (32 -> 64, onto stride-4 coords)
    conv_t<32, 16, false><<<ge2, 256, SM2>>>(xc, w2, m3_in, nullptr, 27, n2, n4, 64, yb);

    // enc2: 2 BasicBlocks, 64ch
    for (int i = 0; i < 2; i++) {
        const float* wA = w_e2 + (size_t)(i * 2 + 0) * 27 * 64 * 64;
        const float* wB = w_e2 + (size_t)(i * 2 + 1) * 27 * 64 * 64;
        conv_t<64, 16, false><<<ge2, 256, SM64>>>(yb, wA, m4_in, nullptr, 27, n4, n4, 64, z1);
        bn_stats<<<STATS_BLOCKS, 256>>>(z1, n4, 64, part);
        bn_reduce<<<1, 256>>>(part, STATS_BLOCKS, 64, n4,
                              g_e2 + (size_t)(i * 2) * 64, b_e2 + (size_t)(i * 2) * 64, par);
        conv_t<64, 16, true><<<ge2, 256, SM64>>>(z1, wB, m4_in, par, 27, n4, n4, 64, z2);
        bn_stats<<<STATS_BLOCKS, 256>>>(z2, n4, 64, part);
        bn_reduce<<<1, 256>>>(part, STATS_BLOCKS, 64, n4,
                              g_e2 + (size_t)(i * 2 + 1) * 64, b_e2 + (size_t)(i * 2 + 1) * 64, par);
        float* dst = (i == 1) ? (float*)d_out : yb;
        bn_res_relu<<<eg4 < 4096 ? eg4 : 4096, 256>>>(
            (const float4*)z2, par, (const float4*)yb, (float4*)dst, n4, 64);
    }
}